// round 14
// baseline (speedup 1.0000x reference)
#include <cuda_runtime.h>

#define MAX_SEG    4096
#define C_PER_SEG  4096          // 64 MB strided CSR — measured faster than 8 MB (R7 vs R10)
#define CHUNK      512

// Scratch starts zeroed (static init) and is re-zeroed at the end of every
// launch sequence (by k_sum), so each graph replay sees clean state.
__device__ int g_cursor[MAX_SEG];
__device__ int g_nidx[MAX_SEG * C_PER_SEG];
__device__ int g_det;                          // published by k_scatter, read by fallback

// ---------------------------------------------------------------- convert + scatter
// 1 element/thread: scatter is atomic-latency-bound; max TLP wins (measured
// 1-elem ~5us < 2-elem ~9us < 4-elem ~10.5us). Dtype detect fused block-
// locally: int64 labels (< n_seg) have all odd int32 words zero; int32 labels
// have values in odd words (nonzero among 256 samples w.p. 1-(1/4096)^256).
__global__ void k_scatter(const void* __restrict__ labels, int n) {
    const int* w = (const int*)labels;
    int tid = threadIdx.x;

    int probe = 2 * tid + 1;                 // odd words 1..511
    int my = (probe < n) ? (w[probe] != 0) : 0;
    int det = __syncthreads_or(my);          // 1 => labels are int32

    if (blockIdx.x == 0 && tid == 0) g_det = det;

    int i = blockIdx.x * blockDim.x + tid;
    if (i < n) {
        int s = det ? w[i] : (int)((const long long*)labels)[i];
        int p = atomicAdd(&g_cursor[s], 1);
        if (p < C_PER_SEG) g_nidx[s * C_PER_SEG + p] = i;
    }
}

// ---------------------------------------------------------------- per-segment gather + mean
// One block per segment (R7 config: ~64us @ 6.15 TB/s, plain loads — __ldcs
// measured SLOWER). PDL: grid launches concurrently with k_scatter's tail;
// cudaGridDependencySynchronize() fences before reading scatter results.
__global__ void __launch_bounds__(128) k_sum(const float* __restrict__ x,
                                             const void* __restrict__ labels,
                                             float* __restrict__ out,
                                             int dim, int n) {
    int seg  = blockIdx.x;
    int tid  = threadIdx.x;
    int dim4 = dim >> 2;               // 120 for dim=480

    __shared__ int sh[CHUNK];
    float4 acc = make_float4(0.f, 0.f, 0.f, 0.f);

    // wait for k_scatter's grid to complete (PDL dependency)
    cudaGridDependencySynchronize();

    int cnt = g_cursor[seg];

    if (cnt <= C_PER_SEG) {
        const int* idx = g_nidx + seg * C_PER_SEG;
        for (int base = 0; base < cnt; base += CHUNK) {
            int m = min(CHUNK, cnt - base);
            __syncthreads();
            for (int i = tid; i < m; i += blockDim.x)
                sh[i] = idx[base + i];
            __syncthreads();

            if (tid < dim4) {
                int j = 0;
                for (; j + 8 <= m; j += 8) {
                    float4 v0 = ((const float4*)(x + (size_t)sh[j + 0] * dim))[tid];
                    float4 v1 = ((const float4*)(x + (size_t)sh[j + 1] * dim))[tid];
                    float4 v2 = ((const float4*)(x + (size_t)sh[j + 2] * dim))[tid];
                    float4 v3 = ((const float4*)(x + (size_t)sh[j + 3] * dim))[tid];
                    float4 v4 = ((const float4*)(x + (size_t)sh[j + 4] * dim))[tid];
                    float4 v5 = ((const float4*)(x + (size_t)sh[j + 5] * dim))[tid];
                    float4 v6 = ((const float4*)(x + (size_t)sh[j + 6] * dim))[tid];
                    float4 v7 = ((const float4*)(x + (size_t)sh[j + 7] * dim))[tid];
                    acc.x += ((v0.x + v1.x) + (v2.x + v3.x)) + ((v4.x + v5.x) + (v6.x + v7.x));
                    acc.y += ((v0.y + v1.y) + (v2.y + v3.y)) + ((v4.y + v5.y) + (v6.y + v7.y));
                    acc.z += ((v0.z + v1.z) + (v2.z + v3.z)) + ((v4.z + v5.z) + (v6.z + v7.z));
                    acc.w += ((v0.w + v1.w) + (v2.w + v3.w)) + ((v4.w + v5.w) + (v6.w + v7.w));
                }
                for (; j + 4 <= m; j += 4) {
                    float4 v0 = ((const float4*)(x + (size_t)sh[j + 0] * dim))[tid];
                    float4 v1 = ((const float4*)(x + (size_t)sh[j + 1] * dim))[tid];
                    float4 v2 = ((const float4*)(x + (size_t)sh[j + 2] * dim))[tid];
                    float4 v3 = ((const float4*)(x + (size_t)sh[j + 3] * dim))[tid];
                    acc.x += (v0.x + v1.x) + (v2.x + v3.x);
                    acc.y += (v0.y + v1.y) + (v2.y + v3.y);
                    acc.z += (v0.z + v1.z) + (v2.z + v3.z);
                    acc.w += (v0.w + v1.w) + (v2.w + v3.w);
                }
                for (; j < m; j++) {
                    float4 v = ((const float4*)(x + (size_t)sh[j] * dim))[tid];
                    acc.x += v.x; acc.y += v.y; acc.z += v.z; acc.w += v.w;
                }
            }
        }
    } else {
        // overflow fallback (P ~ 0 for realistic inputs): scan labels directly
        int det = g_det;
        const int*       w32 = (const int*)labels;
        const long long* w64 = (const long long*)labels;
        for (int i = 0; i < n; i++) {
            int l = det ? w32[i] : (int)w64[i];
            if (l == seg && tid < dim4) {
                float4 v = ((const float4*)(x + (size_t)i * dim))[tid];
                acc.x += v.x; acc.y += v.y; acc.z += v.z; acc.w += v.w;
            }
        }
    }

    if (tid < dim4) {
        float inv = 1.0f / (float)max(cnt, 1);
        float4 o;
        o.x = acc.x * inv;
        o.y = acc.y * inv;
        o.z = acc.z * inv;
        o.w = acc.w * inv;
        __stcs((float4*)(out + (size_t)seg * dim) + tid, o);   // write-once output
    }

    // self-clean scratch for the next graph replay
    if (tid == 127) g_cursor[seg] = 0;
}

// ---------------------------------------------------------------- launch
extern "C" void kernel_launch(void* const* d_in, const int* in_sizes, int n_in,
                              void* d_out, int out_size) {
    const float* x      = (const float*)d_in[0];
    const void*  labels = d_in[1];
    float*       out    = (float*)d_out;

    int n_nodes = in_sizes[1];
    int dim     = in_sizes[0] / n_nodes;      // 480
    int n_seg   = out_size / dim;             // 4096

    k_scatter<<<(n_nodes + 255) / 256, 256>>>((const void*)labels, n_nodes);

    // k_sum with Programmatic Dependent Launch: overlap its launch/ramp with
    // k_scatter's tail; the in-kernel cudaGridDependencySynchronize() fences.
    cudaLaunchConfig_t cfg = {};
    cfg.gridDim  = dim3(n_seg, 1, 1);
    cfg.blockDim = dim3(128, 1, 1);
    cfg.dynamicSmemBytes = 0;
    cfg.stream = 0;
    cudaLaunchAttribute attr[1];
    attr[0].id = cudaLaunchAttributeProgrammaticStreamSerialization;
    attr[0].val.programmaticStreamSerializationAllowed = 1;
    cfg.attrs = attr;
    cfg.numAttrs = 1;
    cudaLaunchKernelEx(&cfg, k_sum, x, (const void*)labels, out, dim, n_nodes);
}

// round 15
// speedup vs baseline: 1.0395x; 1.0395x over previous
#include <cuda_runtime.h>

#define MAX_SEG    4096
#define C_PER_SEG  4096          // 64 MB strided CSR — measured faster than 8 MB (R7 vs R10)
#define CHUNK      512

// Scratch starts zeroed (static init) and is re-zeroed at the end of every
// launch sequence (by k_sum), so each graph replay sees clean state.
__device__ int g_cursor[MAX_SEG];
__device__ int g_nidx[MAX_SEG * C_PER_SEG];
__device__ int g_det;                          // published by k_scatter, read by fallback

// ---------------------------------------------------------------- convert + scatter
// 1 element/thread: scatter is atomic-latency-bound; max TLP wins (measured
// 1-elem ~5us < 2-elem ~9us < 4-elem ~10.5us). Dtype detect fused block-
// locally: int64 labels (< n_seg) have all odd int32 words zero; int32 labels
// have values in odd words (nonzero among 256 samples w.p. 1-(1/4096)^256).
__global__ void k_scatter(const void* __restrict__ labels, int n) {
    const int* w = (const int*)labels;
    int tid = threadIdx.x;

    int probe = 2 * tid + 1;                 // odd words 1..511
    int my = (probe < n) ? (w[probe] != 0) : 0;
    int det = __syncthreads_or(my);          // 1 => labels are int32

    if (blockIdx.x == 0 && tid == 0) g_det = det;

    int i = blockIdx.x * blockDim.x + tid;
    if (i < n) {
        int s = det ? w[i] : (int)((const long long*)labels)[i];
        int p = atomicAdd(&g_cursor[s], 1);
        if (p < C_PER_SEG) g_nidx[s * C_PER_SEG + p] = i;
    }
}

// ---------------------------------------------------------------- per-segment gather + mean
// EXACT R13 loop body (measured 64.1us @ 77.5% DRAM, 32 regs, 86% occ).
// Only change vs R13: PDL dependency sync at the top, so this grid's
// launch/ramp overlaps k_scatter's tail.
__global__ void __launch_bounds__(128) k_sum(const float* __restrict__ x,
                                             const void* __restrict__ labels,
                                             float* __restrict__ out,
                                             int dim, int n) {
    int seg  = blockIdx.x;
    int tid  = threadIdx.x;
    int dim4 = dim >> 2;               // 120 for dim=480

    // wait for k_scatter's grid to complete (PDL dependency fence)
    cudaGridDependencySynchronize();

    int cnt = g_cursor[seg];

    __shared__ int sh[CHUNK];
    float4 acc = make_float4(0.f, 0.f, 0.f, 0.f);

    if (cnt <= C_PER_SEG) {
        const int* idx = g_nidx + seg * C_PER_SEG;
        for (int base = 0; base < cnt; base += CHUNK) {
            int m = min(CHUNK, cnt - base);
            __syncthreads();
            for (int i = tid; i < m; i += blockDim.x)
                sh[i] = idx[base + i];
            __syncthreads();

            if (tid < dim4) {
                int j = 0;
                for (; j + 8 <= m; j += 8) {
                    float4 v0 = ((const float4*)(x + (size_t)sh[j + 0] * dim))[tid];
                    float4 v1 = ((const float4*)(x + (size_t)sh[j + 1] * dim))[tid];
                    float4 v2 = ((const float4*)(x + (size_t)sh[j + 2] * dim))[tid];
                    float4 v3 = ((const float4*)(x + (size_t)sh[j + 3] * dim))[tid];
                    float4 v4 = ((const float4*)(x + (size_t)sh[j + 4] * dim))[tid];
                    float4 v5 = ((const float4*)(x + (size_t)sh[j + 5] * dim))[tid];
                    float4 v6 = ((const float4*)(x + (size_t)sh[j + 6] * dim))[tid];
                    float4 v7 = ((const float4*)(x + (size_t)sh[j + 7] * dim))[tid];
                    acc.x += ((v0.x + v1.x) + (v2.x + v3.x)) + ((v4.x + v5.x) + (v6.x + v7.x));
                    acc.y += ((v0.y + v1.y) + (v2.y + v3.y)) + ((v4.y + v5.y) + (v6.y + v7.y));
                    acc.z += ((v0.z + v1.z) + (v2.z + v3.z)) + ((v4.z + v5.z) + (v6.z + v7.z));
                    acc.w += ((v0.w + v1.w) + (v2.w + v3.w)) + ((v4.w + v5.w) + (v6.w + v7.w));
                }
                for (; j < m; j++) {
                    float4 v = ((const float4*)(x + (size_t)sh[j] * dim))[tid];
                    acc.x += v.x; acc.y += v.y; acc.z += v.z; acc.w += v.w;
                }
            }
        }
    } else {
        // overflow fallback (P ~ 0 for realistic inputs): scan labels directly
        int det = g_det;
        const int*       w32 = (const int*)labels;
        const long long* w64 = (const long long*)labels;
        for (int i = 0; i < n; i++) {
            int l = det ? w32[i] : (int)w64[i];
            if (l == seg && tid < dim4) {
                float4 v = ((const float4*)(x + (size_t)i * dim))[tid];
                acc.x += v.x; acc.y += v.y; acc.z += v.z; acc.w += v.w;
            }
        }
    }

    if (tid < dim4) {
        float inv = 1.0f / (float)max(cnt, 1);
        float4 o;
        o.x = acc.x * inv;
        o.y = acc.y * inv;
        o.z = acc.z * inv;
        o.w = acc.w * inv;
        __stcs((float4*)(out + (size_t)seg * dim) + tid, o);   // write-once output
    }

    // self-clean scratch for the next graph replay
    if (tid == 127) g_cursor[seg] = 0;
}

// ---------------------------------------------------------------- launch
extern "C" void kernel_launch(void* const* d_in, const int* in_sizes, int n_in,
                              void* d_out, int out_size) {
    const float* x      = (const float*)d_in[0];
    const void*  labels = d_in[1];
    float*       out    = (float*)d_out;

    int n_nodes = in_sizes[1];
    int dim     = in_sizes[0] / n_nodes;      // 480
    int n_seg   = out_size / dim;             // 4096

    k_scatter<<<(n_nodes + 255) / 256, 256>>>((const void*)labels, n_nodes);

    // k_sum with Programmatic Dependent Launch: overlap its launch/ramp with
    // k_scatter's tail; the in-kernel cudaGridDependencySynchronize() fences.
    cudaLaunchConfig_t cfg = {};
    cfg.gridDim  = dim3(n_seg, 1, 1);
    cfg.blockDim = dim3(128, 1, 1);
    cfg.dynamicSmemBytes = 0;
    cfg.stream = 0;
    cudaLaunchAttribute attr[1];
    attr[0].id = cudaLaunchAttributeProgrammaticStreamSerialization;
    attr[0].val.programmaticStreamSerializationAllowed = 1;
    cfg.attrs = attr;
    cfg.numAttrs = 1;
    cudaLaunchKernelEx(&cfg, k_sum, x, (const void*)labels, out, dim, n_nodes);
}